// round 8
// baseline (speedup 1.0000x reference)
#include <cuda_runtime.h>
#include <cuda_bf16.h>
#include <cstdint>

// Problem constants (fixed shapes from the reference)
#define N_NODES   100000
#define NFEATS    256
#define HIDDEN    128
#define NCLASS    64
#define BATCH     1024
#define K0        25
#define K1        10
#define NHIST     5
#define ROWS_TOTAL (BATCH + BATCH * K1)   // 11264 layer0 rows
#define GRPB       16                      // rows per gather block
#define GNBLK      (ROWS_TOTAL / GRPB)     // 704 gather blocks
#define WBLK       8                       // extra blocks for W0 transpose/split
#define MTILE      64                      // GEMM M tile
#define GEMM_NBLK  (ROWS_TOTAL / MTILE)    // 176
#define KDIM       (2 * NFEATS)            // 512
#define KCHUNK     64                      // 64 bf16 = 128 B/row (SW128 atom)
#define NCHUNKS    (KDIM / KCHUNK)         // 8
#define FB         8                       // roots per block in final kernel
#define FNBLK      (BATCH / FB)            // 128 blocks

// ---------------- device scratch ----------------
__device__ __align__(16) float         g_L0[(size_t)ROWS_TOTAL * HIDDEN];
__device__ __align__(16) __nv_bfloat16 g_Ahi[(size_t)ROWS_TOTAL * KDIM];  // x hi [row][512]
__device__ __align__(16) __nv_bfloat16 g_Alo[(size_t)ROWS_TOTAL * KDIM];  // x lo
__device__ __align__(16) __nv_bfloat16 g_Bhi[(size_t)HIDDEN * KDIM];      // W0^T hi [n][512]
__device__ __align__(16) __nv_bfloat16 g_Blo[(size_t)HIDDEN * KDIM];      // W0^T lo

#define SMEM_SWIZZLE_128B(o) ((o) ^ (((o) >> 3) & 0x70))

__device__ __forceinline__ uint32_t smem_to_u32(const void* p) {
    uint32_t a;
    asm("{ .reg .u64 t; cvta.to.shared.u64 t, %1; cvt.u32.u64 %0, t; }" : "=r"(a) : "l"(p));
    return a;
}
__device__ __forceinline__ void ldsm_x4(uint32_t addr, uint32_t& r0, uint32_t& r1,
                                        uint32_t& r2, uint32_t& r3) {
    asm volatile("ldmatrix.sync.aligned.m8n8.x4.shared.b16 {%0,%1,%2,%3}, [%4];"
                 : "=r"(r0), "=r"(r1), "=r"(r2), "=r"(r3) : "r"(addr));
}
__device__ __forceinline__ void mma_bf16(float* d, uint32_t a0, uint32_t a1,
                                         uint32_t a2, uint32_t a3,
                                         uint32_t b0, uint32_t b1) {
    asm volatile(
        "mma.sync.aligned.m16n8k16.row.col.f32.bf16.bf16.f32 "
        "{%0,%1,%2,%3}, {%4,%5,%6,%7}, {%8,%9}, {%0,%1,%2,%3};"
        : "+f"(d[0]), "+f"(d[1]), "+f"(d[2]), "+f"(d[3])
        : "r"(a0), "r"(a1), "r"(a2), "r"(a3), "r"(b0), "r"(b1));
}

// ============================================================================
// Kernel 1: gather + mean, emit compensated-bf16 split x to scratch.
// Blocks [0,704): 16 layer0 rows each, 128 threads (thread t = col pair 2t,2t+1).
// Blocks [704,712): transpose+split W0 -> g_Bhi/g_Blo ([n][k] K-major).
// No smem -> max occupancy for gather latency hiding.
// ============================================================================
__global__ __launch_bounds__(128)
void gather_kernel(const float* __restrict__ feats,
                   const float* __restrict__ W0,
                   const int*   __restrict__ nodes,
                   const int*   __restrict__ neighs0,
                   const int*   __restrict__ neighs1,
                   const int*   __restrict__ neighs0_nb)
{
    const int t = threadIdx.x;

    if (blockIdx.x >= GNBLK) {          // ---- W0 transpose + split ----
        const int b = blockIdx.x - GNBLK;
        #pragma unroll 4
        for (int j = 0; j < 64; j++) {
            const int idx = b * 8192 + j * 128 + t;   // idx = k*128 + n
            const int k = idx >> 7, n = idx & 127;
            const float w = W0[idx];
            const __nv_bfloat16 hi = __float2bfloat16(w);
            g_Bhi[(size_t)n * KDIM + k] = hi;
            g_Blo[(size_t)n * KDIM + k] = __float2bfloat16(w - __bfloat162float(hi));
        }
        return;
    }

    const int row0 = blockIdx.x * GRPB;
    const float2* f2 = (const float2*)feats;
    __nv_bfloat162* Ah = (__nv_bfloat162*)g_Ahi;
    __nv_bfloat162* Al = (__nv_bfloat162*)g_Alo;

    #pragma unroll 1
    for (int r = 0; r < GRPB; r++) {
        const int row = row0 + r;
        int self;
        const int* nb;
        if (row < BATCH) {                  // root rows
            self = nodes[row];
            nb   = neighs0 + row * K0;
        } else {                            // neighbor rows
            const int j = row - BATCH;
            self = neighs1[j];
            nb   = neighs0_nb + j * K0;
        }
        const float2 sv = f2[(size_t)self * (NFEATS / 2) + t];
        float sx = 0.f, sy = 0.f;
        #pragma unroll
        for (int k = 0; k < K0; k++) {
            const float2 v = f2[(size_t)nb[k] * (NFEATS / 2) + t];
            sx += v.x; sy += v.y;
        }
        sx *= (1.f / K0);
        sy *= (1.f / K0);

        const size_t base = (size_t)row * (KDIM / 2);
        {
            const __nv_bfloat16 ah = __float2bfloat16(sv.x);
            const __nv_bfloat16 bh = __float2bfloat16(sv.y);
            Ah[base + t] = __halves2bfloat162(ah, bh);
            Al[base + t] = __halves2bfloat162(
                __float2bfloat16(sv.x - __bfloat162float(ah)),
                __float2bfloat16(sv.y - __bfloat162float(bh)));
        }
        {
            const __nv_bfloat16 ah = __float2bfloat16(sx);
            const __nv_bfloat16 bh = __float2bfloat16(sy);
            Ah[base + 128 + t] = __halves2bfloat162(ah, bh);
            Al[base + 128 + t] = __halves2bfloat162(
                __float2bfloat16(sx - __bfloat162float(ah)),
                __float2bfloat16(sy - __bfloat162float(bh)));
        }
    }
}

// ============================================================================
// Kernel 2: warp-MMA bf16 GEMM, D[64,128] = x_tile @ W0 per 64-row tile.
// Compensated: D = Ahi*Bhi + Alo*Bhi + Ahi*Blo, fp32 accumulators.
// 256 threads = 8 warps, warp (w&3, w>>2) owns 16 rows x 64 cols
// (1 m-frag x 8 n-frags of m16n8k16). K chunked at 64; SW128-swizzled smem,
// conflict-free ldmatrix.x4 fragments. Epilogue: +bias, ReLU -> g_L0.
// Dynamic smem: Ahi 8K | Alo 8K | Bhi 16K | Blo 16K | b0s 512B.
// ============================================================================
__global__ __launch_bounds__(256)
void gemm_kernel(const float* __restrict__ b0)
{
    extern __shared__ __align__(1024) char sm[];
    float* b0s = (float*)(sm + 49152);
    const uint32_t smb = smem_to_u32(sm);
    const int tid  = threadIdx.x;
    const int lane = tid & 31;
    const int w    = tid >> 5;
    const int mbase = (w & 3) * 16;     // 4 m-strips of 16 rows
    const int nbase = (w >> 2) * 64;    // 2 n-strips of 64 cols

    for (int i = tid; i < HIDDEN; i += 256) b0s[i] = b0[i];

    const size_t arow0 = (size_t)blockIdx.x * MTILE;
    const char* Ahi = (const char*)g_Ahi + arow0 * (KDIM * 2);
    const char* Alo = (const char*)g_Alo + arow0 * (KDIM * 2);

    float acc[8][4];
    #pragma unroll
    for (int j = 0; j < 8; j++)
        #pragma unroll
        for (int q = 0; q < 4; q++) acc[j][q] = 0.f;

    // per-thread ldmatrix smem offsets (row/kbyte pattern is loop-invariant)
    const int a_row = (lane & 15);              // + mbase
    const int a_kb  = (lane >> 4) * 16;         // + ks*32
    const int b_nr  = ((lane >> 4) * 8) + (lane & 7);   // + nbase + j*16
    const int b_kb  = ((lane >> 3) & 1) * 16;   // + ks*32

    #pragma unroll 1
    for (int ch = 0; ch < NCHUNKS; ch++) {
        // ---- stage tiles (16B per store, swizzled; conflict-free) ----
        #pragma unroll
        for (int r = 0; r < 2; r++) {           // A: 64 rows x 8 chunks
            const int i = r * 256 + tid;
            const int row = i >> 3, c = i & 7;
            const size_t so = (size_t)row * (KDIM * 2) + ch * 128 + c * 16;
            const uint32_t doff = SMEM_SWIZZLE_128B(row * 128 + c * 16);
            *(uint4*)(sm + doff)        = *(const uint4*)(Ahi + so);
            *(uint4*)(sm + 8192 + doff) = *(const uint4*)(Alo + so);
        }
        #pragma unroll
        for (int r = 0; r < 4; r++) {           // B: 128 rows x 8 chunks
            const int i = r * 256 + tid;
            const int row = i >> 3, c = i & 7;
            const size_t so = (size_t)row * (KDIM * 2) + ch * 128 + c * 16;
            const uint32_t doff = SMEM_SWIZZLE_128B(row * 128 + c * 16);
            *(uint4*)(sm + 16384 + doff) = *(const uint4*)((const char*)g_Bhi + so);
            *(uint4*)(sm + 32768 + doff) = *(const uint4*)((const char*)g_Blo + so);
        }
        __syncthreads();

        // ---- 3 compensated products x 4 k-steps ----
        #pragma unroll
        for (int p = 0; p < 3; p++) {
            const uint32_t abase = smb + ((p == 1) ? 8192u : 0u);
            const uint32_t bbase = smb + ((p == 2) ? 32768u : 16384u);
            #pragma unroll
            for (int ks = 0; ks < 4; ks++) {
                uint32_t a0, a1, a2, a3;
                ldsm_x4(abase + SMEM_SWIZZLE_128B((mbase + a_row) * 128
                                                  + ks * 32 + a_kb),
                        a0, a1, a2, a3);
                #pragma unroll
                for (int j = 0; j < 4; j++) {   // pairs of n-tiles
                    uint32_t q0, q1, q2, q3;
                    ldsm_x4(bbase + SMEM_SWIZZLE_128B((nbase + j * 16 + b_nr) * 128
                                                      + ks * 32 + b_kb),
                            q0, q1, q2, q3);
                    mma_bf16(acc[2 * j],     a0, a1, a2, a3, q0, q1);
                    mma_bf16(acc[2 * j + 1], a0, a1, a2, a3, q2, q3);
                }
            }
        }
        __syncthreads();
    }

    // ---- epilogue: +bias, ReLU ----
    const int g  = lane >> 2;
    const int tq = lane & 3;
    #pragma unroll
    for (int j = 0; j < 8; j++) {
        const int col = nbase + j * 8 + 2 * tq;
        const float bb0 = b0s[col], bb1 = b0s[col + 1];
        const size_t r0g = arow0 + mbase + g;
        float2 v0 = make_float2(fmaxf(acc[j][0] + bb0, 0.f),
                                fmaxf(acc[j][1] + bb1, 0.f));
        float2 v1 = make_float2(fmaxf(acc[j][2] + bb0, 0.f),
                                fmaxf(acc[j][3] + bb1, 0.f));
        *(float2*)&g_L0[r0g * HIDDEN + col]       = v0;
        *(float2*)&g_L0[(r0g + 8) * HIDDEN + col] = v1;
    }
}

// ============================================================================
// Kernel 3: per root node b:
//   mean_t = ( sum_j 0.5*(neigh_original[b,j,t] - history[neighs1[b,j],t])
//            + sum_i history[h_nodes[b,i],t] ) / 15
//   y = [h1[b] | mean];  out[b] = relu(y @ W1 + b1)
// 128 blocks x 256 threads, W1 staged in smem, 8 roots/block, 4-way split-K.
// ============================================================================
__global__ __launch_bounds__(256)
void final_kernel(const float* __restrict__ history,
                  const float* __restrict__ W1,
                  const float* __restrict__ b1,
                  const int*   __restrict__ neighs1,
                  const int*   __restrict__ h_nodes,
                  float*       __restrict__ out)
{
    extern __shared__ float smf[];
    float* W1s = smf;                        // 16384 floats (64 KB)
    float* ys  = smf + 2 * HIDDEN * NCLASS;  // FB*256
    float* red = ys + FB * 2 * HIDDEN;       // FB*4*64

    const int t   = threadIdx.x;
    const int b0r = blockIdx.x * FB;

    for (int i = t; i < (2 * HIDDEN * NCLASS) / 4; i += 256)
        ((float4*)W1s)[i] = ((const float4*)W1)[i];

    for (int i = t; i < FB * HIDDEN; i += 256) {
        const int r = i >> 7, c = i & 127;
        ys[r * 2 * HIDDEN + c] = g_L0[(size_t)(b0r + r) * HIDDEN + c];
    }

    {
        const int half = t >> 7;
        const int tc   = t & 127;
        #pragma unroll 1
        for (int rr = 0; rr < FB / 2; rr++) {
            const int r = rr * 2 + half;
            const int b = b0r + r;
            float s = 0.f;
            #pragma unroll
            for (int j = 0; j < K1; j++) {
                const int n1 = neighs1[b * K1 + j];
                const float no = g_L0[(size_t)(BATCH + b * K1 + j) * HIDDEN + tc];
                s += 0.5f * (no - history[(size_t)n1 * HIDDEN + tc]);
            }
            #pragma unroll
            for (int j = 0; j < NHIST; j++) {
                const int hn = h_nodes[b * NHIST + j];
                s += history[(size_t)hn * HIDDEN + tc];
            }
            ys[r * 2 * HIDDEN + HIDDEN + tc] = s * (1.f / (K1 + NHIST));
        }
    }
    __syncthreads();

    const int o  = t & 63;
    const int s4 = t >> 6;
    float acc[FB];
    #pragma unroll
    for (int r = 0; r < FB; r++) acc[r] = 0.f;
    #pragma unroll 4
    for (int kk = 0; kk < (2 * HIDDEN) / 4; kk++) {
        const int k = s4 * ((2 * HIDDEN) / 4) + kk;
        const float wv = W1s[k * NCLASS + o];
        #pragma unroll
        for (int r = 0; r < FB; r++)
            acc[r] += ys[r * 2 * HIDDEN + k] * wv;
    }
    #pragma unroll
    for (int r = 0; r < FB; r++) red[(r * 4 + s4) * 64 + o] = acc[r];
    __syncthreads();

    for (int i = t; i < FB * NCLASS; i += 256) {
        const int r = i >> 6, o2 = i & 63;
        const float v = red[(r * 4 + 0) * 64 + o2] + red[(r * 4 + 1) * 64 + o2]
                      + red[(r * 4 + 2) * 64 + o2] + red[(r * 4 + 3) * 64 + o2];
        out[(size_t)(b0r + r) * NCLASS + o2] = fmaxf(v + b1[o2], 0.f);
    }
}

// ============================================================================
// kernel_launch — graph-capturable, allocation-free.
// Input order: feats, history, W0, b0, W1, b1, nodes, neighs0, neighs1,
// neighs0_nb, h_nodes. Output: float32 [1024, 64].
// ============================================================================
extern "C" void kernel_launch(void* const* d_in, const int* in_sizes, int n_in,
                              void* d_out, int out_size)
{
    const float* feats      = (const float*)d_in[0];
    const float* history    = (const float*)d_in[1];
    const float* W0         = (const float*)d_in[2];
    const float* b0         = (const float*)d_in[3];
    const float* W1         = (const float*)d_in[4];
    const float* b1         = (const float*)d_in[5];
    const int*   nodes      = (const int*)d_in[6];
    const int*   neighs0    = (const int*)d_in[7];
    const int*   neighs1    = (const int*)d_in[8];
    const int*   neighs0_nb = (const int*)d_in[9];
    const int*   h_nodes    = (const int*)d_in[10];
    float* out = (float*)d_out;

    const int gemm_smem  = 49152 + 512;   // A/B tiles + staged bias
    const int final_smem = (2 * HIDDEN * NCLASS + FB * 2 * HIDDEN + FB * 4 * 64)
                           * (int)sizeof(float);   // 80 KB
    cudaFuncSetAttribute(gemm_kernel, cudaFuncAttributeMaxDynamicSharedMemorySize,
                         gemm_smem);
    cudaFuncSetAttribute(final_kernel, cudaFuncAttributeMaxDynamicSharedMemorySize,
                         final_smem);

    gather_kernel<<<GNBLK + WBLK, 128>>>(feats, W0, nodes, neighs0, neighs1,
                                         neighs0_nb);
    gemm_kernel<<<GEMM_NBLK, 256, gemm_smem>>>(b0);
    final_kernel<<<FNBLK, 256, final_smem>>>(history, W1, b1, neighs1, h_nodes, out);
}

// round 9
// speedup vs baseline: 1.4068x; 1.4068x over previous
#include <cuda_runtime.h>
#include <cuda_bf16.h>
#include <cstdint>

// Problem constants (fixed shapes from the reference)
#define N_NODES   100000
#define NFEATS    256
#define HIDDEN    128
#define NCLASS    64
#define BATCH     1024
#define K0        25
#define K1        10
#define NHIST     5
#define ROWS_TOTAL (BATCH + BATCH * K1)   // 11264 layer0 rows
#define WBLK       8                       // extra blocks for W0 transpose/split
#define MTILE      64                      // GEMM M tile
#define GEMM_NBLK  (ROWS_TOTAL / MTILE)    // 176
#define KDIM       (2 * NFEATS)            // 512
#define KCHUNK     64                      // 64 bf16 = 128 B/row (SW128 atom)
#define NCHUNKS    (KDIM / KCHUNK)         // 8
#define FB         8                       // roots per block in final kernel
#define FNBLK      (BATCH / FB)            // 128 blocks
#define BUFSZ      49152                   // one GEMM stage: A 2x8K + B 2x16K

// ---------------- device scratch ----------------
__device__ __align__(16) float         g_L0[(size_t)ROWS_TOTAL * HIDDEN];
__device__ __align__(16) __nv_bfloat16 g_Ahi[(size_t)ROWS_TOTAL * KDIM];  // x hi [row][512]
__device__ __align__(16) __nv_bfloat16 g_Alo[(size_t)ROWS_TOTAL * KDIM];  // x lo
__device__ __align__(16) __nv_bfloat16 g_Bhi[(size_t)HIDDEN * KDIM];      // W0^T hi [n][512]
__device__ __align__(16) __nv_bfloat16 g_Blo[(size_t)HIDDEN * KDIM];      // W0^T lo

#define SMEM_SWIZZLE_128B(o) ((o) ^ (((o) >> 3) & 0x70))

__device__ __forceinline__ uint32_t smem_to_u32(const void* p) {
    uint32_t a;
    asm("{ .reg .u64 t; cvta.to.shared.u64 t, %1; cvt.u32.u64 %0, t; }" : "=r"(a) : "l"(p));
    return a;
}
__device__ __forceinline__ void cp_async16(uint32_t dst, const void* src) {
    asm volatile("cp.async.cg.shared.global [%0], [%1], 16;" :: "r"(dst), "l"(src));
}
#define CP_COMMIT()  asm volatile("cp.async.commit_group;" ::: "memory")
#define CP_WAIT(n)   asm volatile("cp.async.wait_group %0;" :: "n"(n) : "memory")

__device__ __forceinline__ void ldsm_x4(uint32_t addr, uint32_t& r0, uint32_t& r1,
                                        uint32_t& r2, uint32_t& r3) {
    asm volatile("ldmatrix.sync.aligned.m8n8.x4.shared.b16 {%0,%1,%2,%3}, [%4];"
                 : "=r"(r0), "=r"(r1), "=r"(r2), "=r"(r3) : "r"(addr));
}
__device__ __forceinline__ void mma_bf16(float* d, uint32_t a0, uint32_t a1,
                                         uint32_t a2, uint32_t a3,
                                         uint32_t b0, uint32_t b1) {
    asm volatile(
        "mma.sync.aligned.m16n8k16.row.col.f32.bf16.bf16.f32 "
        "{%0,%1,%2,%3}, {%4,%5,%6,%7}, {%8,%9}, {%0,%1,%2,%3};"
        : "+f"(d[0]), "+f"(d[1]), "+f"(d[2]), "+f"(d[3])
        : "r"(a0), "r"(a1), "r"(a2), "r"(a3), "r"(b0), "r"(b1));
}

// ============================================================================
// Kernel 1: gather + mean, emit compensated-bf16 split x to scratch.
// ONE layer0 row per 128-thread block (blocks [0,11264)) -> ~full occupancy
// for gather latency hiding (R7 measured occ=28% at 16 rows/block).
// Blocks [11264,11272): transpose+split W0 -> g_Bhi/g_Blo ([n][k] K-major).
// ============================================================================
__global__ __launch_bounds__(128)
void gather_kernel(const float* __restrict__ feats,
                   const float* __restrict__ W0,
                   const int*   __restrict__ nodes,
                   const int*   __restrict__ neighs0,
                   const int*   __restrict__ neighs1,
                   const int*   __restrict__ neighs0_nb)
{
    const int t = threadIdx.x;

    if (blockIdx.x >= ROWS_TOTAL) {     // ---- W0 transpose + split ----
        const int b = blockIdx.x - ROWS_TOTAL;
        #pragma unroll 4
        for (int j = 0; j < 64; j++) {
            const int idx = b * 8192 + j * 128 + t;   // idx = k*128 + n
            const int k = idx >> 7, n = idx & 127;
            const float w = W0[idx];
            const __nv_bfloat16 hi = __float2bfloat16(w);
            g_Bhi[(size_t)n * KDIM + k] = hi;
            g_Blo[(size_t)n * KDIM + k] = __float2bfloat16(w - __bfloat162float(hi));
        }
        return;
    }

    const int row = blockIdx.x;
    const float2* f2 = (const float2*)feats;
    __nv_bfloat162* Ah = (__nv_bfloat162*)g_Ahi;
    __nv_bfloat162* Al = (__nv_bfloat162*)g_Alo;

    int self;
    const int* nb;
    if (row < BATCH) {                  // root rows
        self = nodes[row];
        nb   = neighs0 + row * K0;
    } else {                            // neighbor rows
        const int j = row - BATCH;
        self = neighs1[j];
        nb   = neighs0_nb + j * K0;
    }
    const float2 sv = f2[(size_t)self * (NFEATS / 2) + t];
    float sx = 0.f, sy = 0.f;
    #pragma unroll
    for (int k = 0; k < K0; k++) {
        const float2 v = f2[(size_t)nb[k] * (NFEATS / 2) + t];
        sx += v.x; sy += v.y;
    }
    sx *= (1.f / K0);
    sy *= (1.f / K0);

    const size_t base = (size_t)row * (KDIM / 2);
    {
        const __nv_bfloat16 ah = __float2bfloat16(sv.x);
        const __nv_bfloat16 bh = __float2bfloat16(sv.y);
        Ah[base + t] = __halves2bfloat162(ah, bh);
        Al[base + t] = __halves2bfloat162(
            __float2bfloat16(sv.x - __bfloat162float(ah)),
            __float2bfloat16(sv.y - __bfloat162float(bh)));
    }
    {
        const __nv_bfloat16 ah = __float2bfloat16(sx);
        const __nv_bfloat16 bh = __float2bfloat16(sy);
        Ah[base + 128 + t] = __halves2bfloat162(ah, bh);
        Al[base + 128 + t] = __halves2bfloat162(
            __float2bfloat16(sx - __bfloat162float(ah)),
            __float2bfloat16(sy - __bfloat162float(bh)));
    }
}

// ============================================================================
// Kernel 2: warp-MMA bf16 GEMM, D[64,128] = x_tile @ W0 per 64-row tile.
// Compensated: D = Ahi*Bhi + Alo*Bhi + Ahi*Blo, fp32 accumulators.
// 256 threads = 8 warps, warp (w&3, w>>2) owns 16 rows x 64 cols.
// K chunked at 64; DOUBLE-BUFFERED cp.async pipeline (prefetch chunk ch+1
// while computing ch) hides gmem latency that R7's lockstep version exposed.
// Dynamic smem: 2 x 48 KB stages + 512 B bias.
// Stage layout: Ahi 0 | Alo 8192 | Bhi 16384 | Blo 32768.
// ============================================================================
__global__ __launch_bounds__(256)
void gemm_kernel(const float* __restrict__ b0)
{
    extern __shared__ __align__(1024) char sm[];
    float* b0s = (float*)(sm + 2 * BUFSZ);
    const uint32_t smb = smem_to_u32(sm);
    const int tid  = threadIdx.x;
    const int lane = tid & 31;
    const int w    = tid >> 5;
    const int mbase = (w & 3) * 16;     // 4 m-strips of 16 rows
    const int nbase = (w >> 2) * 64;    // 2 n-strips of 64 cols

    for (int i = tid; i < HIDDEN; i += 256) b0s[i] = b0[i];

    const size_t arow0 = (size_t)blockIdx.x * MTILE;
    const char* Ahi = (const char*)g_Ahi + arow0 * (KDIM * 2);
    const char* Alo = (const char*)g_Alo + arow0 * (KDIM * 2);

    // per-thread copy addressing (loop-invariant)
    const int ar  = (tid >> 2);              // A row 0..63   (4 thr x 16B = row)
    const int ac  = (tid & 3) * 2;           // A 16B-col 0/2/4/6
    const int br  = (tid >> 1);              // B row 0..127  (2 thr x 16B... )
    // A: 64 rows x 128 B = 8192 B = 512 x 16B; 256 threads -> 2 x 16B each
    // B: 128 rows x 128 B = 16384 B;          256 threads -> 4 x 16B each

    auto copy_chunk = [&](int ch, uint32_t bufo) {
        // A tiles: thread covers (ar, ac) and (ar, ac+1)
        #pragma unroll
        for (int q = 0; q < 2; q++) {
            const int c = ac + q;
            const size_t so = (size_t)ar * (KDIM * 2) + ch * 128 + c * 16;
            const uint32_t doff = SMEM_SWIZZLE_128B(ar * 128 + c * 16);
            cp_async16(smb + bufo + doff,        Ahi + so);
            cp_async16(smb + bufo + 8192 + doff, Alo + so);
        }
        // B tiles: thread covers rows br, br with 16B-cols (tid&1)*4 + q
        #pragma unroll
        for (int q = 0; q < 4; q++) {
            const int c = (tid & 1) * 4 + q;
            const size_t so = (size_t)br * (KDIM * 2) + ch * 128 + c * 16;
            const uint32_t doff = SMEM_SWIZZLE_128B(br * 128 + c * 16);
            cp_async16(smb + bufo + 16384 + doff, (const char*)g_Bhi + so);
            cp_async16(smb + bufo + 32768 + doff, (const char*)g_Blo + so);
        }
        CP_COMMIT();
    };

    float acc[8][4];
    #pragma unroll
    for (int j = 0; j < 8; j++)
        #pragma unroll
        for (int q = 0; q < 4; q++) acc[j][q] = 0.f;

    // per-thread ldmatrix smem offsets
    const int a_row = (lane & 15);              // + mbase
    const int a_kb  = (lane >> 4) * 16;         // + ks*32
    const int b_nr  = ((lane >> 4) * 8) + (lane & 7);   // + nbase + j*16
    const int b_kb  = ((lane >> 3) & 1) * 16;   // + ks*32

    copy_chunk(0, 0);

    #pragma unroll 1
    for (int ch = 0; ch < NCHUNKS; ch++) {
        const uint32_t bufo = (ch & 1) * BUFSZ;
        if (ch + 1 < NCHUNKS) {
            copy_chunk(ch + 1, ((ch + 1) & 1) * BUFSZ);
            CP_WAIT(1);                 // current chunk's group complete
        } else {
            CP_WAIT(0);
        }
        __syncthreads();

        // ---- 3 compensated products x 4 k-steps ----
        #pragma unroll
        for (int p = 0; p < 3; p++) {
            const uint32_t abase = smb + bufo + ((p == 1) ? 8192u : 0u);
            const uint32_t bbase = smb + bufo + ((p == 2) ? 32768u : 16384u);
            #pragma unroll
            for (int ks = 0; ks < 4; ks++) {
                uint32_t a0, a1, a2, a3;
                ldsm_x4(abase + SMEM_SWIZZLE_128B((mbase + a_row) * 128
                                                  + ks * 32 + a_kb),
                        a0, a1, a2, a3);
                #pragma unroll
                for (int j = 0; j < 4; j++) {   // pairs of n-tiles
                    uint32_t q0, q1, q2, q3;
                    ldsm_x4(bbase + SMEM_SWIZZLE_128B((nbase + j * 16 + b_nr) * 128
                                                      + ks * 32 + b_kb),
                            q0, q1, q2, q3);
                    mma_bf16(acc[2 * j],     a0, a1, a2, a3, q0, q1);
                    mma_bf16(acc[2 * j + 1], a0, a1, a2, a3, q2, q3);
                }
            }
        }
        __syncthreads();   // all reads of bufo done before it is refilled (ch+2)
    }

    // ---- epilogue: +bias, ReLU ----
    const int g  = lane >> 2;
    const int tq = lane & 3;
    #pragma unroll
    for (int j = 0; j < 8; j++) {
        const int col = nbase + j * 8 + 2 * tq;
        const float bb0 = b0s[col], bb1 = b0s[col + 1];
        const size_t r0g = arow0 + mbase + g;
        float2 v0 = make_float2(fmaxf(acc[j][0] + bb0, 0.f),
                                fmaxf(acc[j][1] + bb1, 0.f));
        float2 v1 = make_float2(fmaxf(acc[j][2] + bb0, 0.f),
                                fmaxf(acc[j][3] + bb1, 0.f));
        *(float2*)&g_L0[r0g * HIDDEN + col]       = v0;
        *(float2*)&g_L0[(r0g + 8) * HIDDEN + col] = v1;
    }
}

// ============================================================================
// Kernel 3: per root node b:
//   mean_t = ( sum_j 0.5*(neigh_original[b,j,t] - history[neighs1[b,j],t])
//            + sum_i history[h_nodes[b,i],t] ) / 15
//   y = [h1[b] | mean];  out[b] = relu(y @ W1 + b1)
// 128 blocks x 256 threads, W1 staged in smem, 8 roots/block, 4-way split-K.
// ============================================================================
__global__ __launch_bounds__(256)
void final_kernel(const float* __restrict__ history,
                  const float* __restrict__ W1,
                  const float* __restrict__ b1,
                  const int*   __restrict__ neighs1,
                  const int*   __restrict__ h_nodes,
                  float*       __restrict__ out)
{
    extern __shared__ float smf[];
    float* W1s = smf;                        // 16384 floats (64 KB)
    float* ys  = smf + 2 * HIDDEN * NCLASS;  // FB*256
    float* red = ys + FB * 2 * HIDDEN;       // FB*4*64

    const int t   = threadIdx.x;
    const int b0r = blockIdx.x * FB;

    for (int i = t; i < (2 * HIDDEN * NCLASS) / 4; i += 256)
        ((float4*)W1s)[i] = ((const float4*)W1)[i];

    for (int i = t; i < FB * HIDDEN; i += 256) {
        const int r = i >> 7, c = i & 127;
        ys[r * 2 * HIDDEN + c] = g_L0[(size_t)(b0r + r) * HIDDEN + c];
    }

    {
        const int half = t >> 7;
        const int tc   = t & 127;
        #pragma unroll 1
        for (int rr = 0; rr < FB / 2; rr++) {
            const int r = rr * 2 + half;
            const int b = b0r + r;
            float s = 0.f;
            #pragma unroll
            for (int j = 0; j < K1; j++) {
                const int n1 = neighs1[b * K1 + j];
                const float no = g_L0[(size_t)(BATCH + b * K1 + j) * HIDDEN + tc];
                s += 0.5f * (no - history[(size_t)n1 * HIDDEN + tc]);
            }
            #pragma unroll
            for (int j = 0; j < NHIST; j++) {
                const int hn = h_nodes[b * NHIST + j];
                s += history[(size_t)hn * HIDDEN + tc];
            }
            ys[r * 2 * HIDDEN + HIDDEN + tc] = s * (1.f / (K1 + NHIST));
        }
    }
    __syncthreads();

    const int o  = t & 63;
    const int s4 = t >> 6;
    float acc[FB];
    #pragma unroll
    for (int r = 0; r < FB; r++) acc[r] = 0.f;
    #pragma unroll 4
    for (int kk = 0; kk < (2 * HIDDEN) / 4; kk++) {
        const int k = s4 * ((2 * HIDDEN) / 4) + kk;
        const float wv = W1s[k * NCLASS + o];
        #pragma unroll
        for (int r = 0; r < FB; r++)
            acc[r] += ys[r * 2 * HIDDEN + k] * wv;
    }
    #pragma unroll
    for (int r = 0; r < FB; r++) red[(r * 4 + s4) * 64 + o] = acc[r];
    __syncthreads();

    for (int i = t; i < FB * NCLASS; i += 256) {
        const int r = i >> 6, o2 = i & 63;
        const float v = red[(r * 4 + 0) * 64 + o2] + red[(r * 4 + 1) * 64 + o2]
                      + red[(r * 4 + 2) * 64 + o2] + red[(r * 4 + 3) * 64 + o2];
        out[(size_t)(b0r + r) * NCLASS + o2] = fmaxf(v + b1[o2], 0.f);
    }
}

// ============================================================================
// kernel_launch — graph-capturable, allocation-free.
// Input order: feats, history, W0, b0, W1, b1, nodes, neighs0, neighs1,
// neighs0_nb, h_nodes. Output: float32 [1024, 64].
// ============================================================================
extern "C" void kernel_launch(void* const* d_in, const int* in_sizes, int n_in,
                              void* d_out, int out_size)
{
    const float* feats      = (const float*)d_in[0];
    const float* history    = (const float*)d_in[1];
    const float* W0         = (const float*)d_in[2];
    const float* b0         = (const float*)d_in[3];
    const float* W1         = (const float*)d_in[4];
    const float* b1         = (const float*)d_in[5];
    const int*   nodes      = (const int*)d_in[6];
    const int*   neighs0    = (const int*)d_in[7];
    const int*   neighs1    = (const int*)d_in[8];
    const int*   neighs0_nb = (const int*)d_in[9];
    const int*   h_nodes    = (const int*)d_in[10];
    float* out = (float*)d_out;

    const int gemm_smem  = 2 * BUFSZ + 512;   // 96.5 KB: double-buffered stages
    const int final_smem = (2 * HIDDEN * NCLASS + FB * 2 * HIDDEN + FB * 4 * 64)
                           * (int)sizeof(float);   // 80 KB
    cudaFuncSetAttribute(gemm_kernel, cudaFuncAttributeMaxDynamicSharedMemorySize,
                         gemm_smem);
    cudaFuncSetAttribute(final_kernel, cudaFuncAttributeMaxDynamicSharedMemorySize,
                         final_smem);

    gather_kernel<<<ROWS_TOTAL + WBLK, 128>>>(feats, W0, nodes, neighs0, neighs1,
                                              neighs0_nb);
    gemm_kernel<<<GEMM_NBLK, 256, gemm_smem>>>(b0);
    final_kernel<<<FNBLK, 256, final_smem>>>(history, W1, b1, neighs1, h_nodes, out);
}

// round 11
// speedup vs baseline: 1.5119x; 1.0747x over previous
#include <cuda_runtime.h>
#include <cuda_bf16.h>
#include <cstdint>

// Problem constants (fixed shapes from the reference)
#define N_NODES   100000
#define NFEATS    256
#define HIDDEN    128
#define NCLASS    64
#define BATCH     1024
#define K0        25
#define K1        10
#define NHIST     5
#define ROWS_TOTAL (BATCH + BATCH * K1)   // 11264 layer0 rows
#define GROWBLK    (ROWS_TOTAL / 2)        // 5632 gather blocks (2 rows each)
#define WBLK       8                       // extra blocks for W0 transpose
#define MTILE      64                      // GEMM M tile
#define GEMM_NBLK  (ROWS_TOTAL / MTILE)    // 176
#define KDIM       (2 * NFEATS)            // 512
#define KCHUNK     64                      // 64 f32 = 256 B/row = 2 x 128B planes
#define NCHUNKS    (KDIM / KCHUNK)         // 8
#define FB         8                       // roots per block in final kernel
#define FNBLK      (BATCH / FB)            // 128 blocks
#define BUFSZ      49152                   // stage: A 2x8K planes + B 2x16K planes

// ---------------- device scratch ----------------
__device__ __align__(16) float g_L0[(size_t)ROWS_TOTAL * HIDDEN];
__device__ __align__(16) float g_A[(size_t)ROWS_TOTAL * KDIM];   // tf32-rounded x
__device__ __align__(16) float g_B[(size_t)HIDDEN * KDIM];       // tf32 W0^T [n][k]

#define SMEM_SWIZZLE_128B(o) ((o) ^ (((o) >> 3) & 0x70))

__device__ __forceinline__ uint32_t smem_to_u32(const void* p) {
    uint32_t a;
    asm("{ .reg .u64 t; cvta.to.shared.u64 t, %1; cvt.u32.u64 %0, t; }" : "=r"(a) : "l"(p));
    return a;
}
__device__ __forceinline__ float tf32_rna(float x) {
    uint32_t r;
    asm("cvt.rna.tf32.f32 %0, %1;" : "=r"(r) : "f"(x));
    return __uint_as_float(r);
}
__device__ __forceinline__ void cp_async16(uint32_t dst, const void* src) {
    asm volatile("cp.async.cg.shared.global [%0], [%1], 16;" :: "r"(dst), "l"(src));
}
#define CP_COMMIT()  asm volatile("cp.async.commit_group;" ::: "memory")
#define CP_WAIT(n)   asm volatile("cp.async.wait_group %0;" :: "n"(n) : "memory")

__device__ __forceinline__ void ldsm_x4(uint32_t addr, uint32_t& r0, uint32_t& r1,
                                        uint32_t& r2, uint32_t& r3) {
    asm volatile("ldmatrix.sync.aligned.m8n8.x4.shared.b16 {%0,%1,%2,%3}, [%4];"
                 : "=r"(r0), "=r"(r1), "=r"(r2), "=r"(r3) : "r"(addr));
}
__device__ __forceinline__ void mma_tf32(float* d, uint32_t a0, uint32_t a1,
                                         uint32_t a2, uint32_t a3,
                                         uint32_t b0, uint32_t b1) {
    asm volatile(
        "mma.sync.aligned.m16n8k8.row.col.f32.tf32.tf32.f32 "
        "{%0,%1,%2,%3}, {%4,%5,%6,%7}, {%8,%9}, {%0,%1,%2,%3};"
        : "+f"(d[0]), "+f"(d[1]), "+f"(d[2]), "+f"(d[3])
        : "r"(a0), "r"(a1), "r"(a2), "r"(a3), "r"(b0), "r"(b1));
}

// ============================================================================
// Kernel 1: gather + mean -> tf32-rounded fp32 scratch.
// Blocks [0,5632): TWO layer0 rows per 128-thread block; each 64-thread half
// handles one row with float4 (LDG.128) gathers.
// Blocks [5632,5640): transpose W0 -> g_B ([n][k] K-major, tf32-rounded).
//   FULL coverage: 8 blocks x 64 iters x 128 threads = 65536 = all of W0
//   (R9 bug: only 32 iters -> half of g_B was garbage -> rel_err 0.17).
// ============================================================================
__global__ __launch_bounds__(128)
void gather_kernel(const float* __restrict__ feats,
                   const float* __restrict__ W0,
                   const int*   __restrict__ nodes,
                   const int*   __restrict__ neighs0,
                   const int*   __restrict__ neighs1,
                   const int*   __restrict__ neighs0_nb)
{
    const int t = threadIdx.x;

    if (blockIdx.x >= GROWBLK) {        // ---- W0 transpose (tf32) ----
        const int b = blockIdx.x - GROWBLK;
        #pragma unroll 4
        for (int j = 0; j < 64; j++) {
            const int idx = b * 8192 + j * 128 + t;   // idx = k*128 + n
            const int k = idx >> 7, n = idx & 127;
            g_B[(size_t)n * KDIM + k] = tf32_rna(W0[idx]);
        }
        return;
    }

    const int half = t >> 6;            // which of the 2 rows
    const int tc   = t & 63;            // float4 column group
    const int row  = blockIdx.x * 2 + half;
    const float4* f4 = (const float4*)feats;

    int self;
    const int* nb;
    if (row < BATCH) {                  // root rows
        self = nodes[row];
        nb   = neighs0 + row * K0;
    } else {                            // neighbor rows
        const int j = row - BATCH;
        self = neighs1[j];
        nb   = neighs0_nb + j * K0;
    }
    const float4 sv = f4[(size_t)self * (NFEATS / 4) + tc];
    float s0 = 0.f, s1 = 0.f, s2 = 0.f, s3 = 0.f;
    #pragma unroll
    for (int k = 0; k < K0; k++) {
        const float4 v = f4[(size_t)nb[k] * (NFEATS / 4) + tc];
        s0 += v.x; s1 += v.y; s2 += v.z; s3 += v.w;
    }
    const float inv = 1.f / K0;

    float4* A4 = (float4*)(g_A + (size_t)row * KDIM);
    A4[tc] = make_float4(tf32_rna(sv.x), tf32_rna(sv.y),
                         tf32_rna(sv.z), tf32_rna(sv.w));
    A4[64 + tc] = make_float4(tf32_rna(s0 * inv), tf32_rna(s1 * inv),
                              tf32_rna(s2 * inv), tf32_rna(s3 * inv));
}

// ============================================================================
// Kernel 2: warp-MMA TF32 GEMM, D[64,128] = x_tile @ W0 per 64-row tile.
// Single product (tf32-rounded inputs), fp32 accumulate.
// 256 threads = 8 warps, warp (w&3, w>>2) owns 16 rows x 64 cols
// (m16n8k8: 8 k-steps/chunk x 8 n-frags). Double-buffered cp.async.
// Stage layout (48 KB), 128B "planes" so ldmatrix stays conflict-free:
//   A k[0,32): 0 | A k[32,64): 8K | B k[0,32): 16K | B k[32,64): 32K
// Fragment maps verified against PTX ISA m16n8k8.tf32 tables:
//   A: a0 r=lane>>2,c=lane&3; a1 r+8; a2 c+4; a3 r+8,c+4  (ldsm tiles 0..3)
//   B: b0 k=lane&3,n=lane>>2; b1 k+4                      (ldsm tile pairs)
// ============================================================================
__global__ __launch_bounds__(256)
void gemm_kernel(const float* __restrict__ b0)
{
    extern __shared__ __align__(1024) char sm[];
    float* b0s = (float*)(sm + 2 * BUFSZ);
    const uint32_t smb = smem_to_u32(sm);
    const int tid  = threadIdx.x;
    const int lane = tid & 31;
    const int w    = tid >> 5;
    const int mbase = (w & 3) * 16;     // 4 m-strips of 16 rows
    const int nbase = (w >> 2) * 64;    // 2 n-strips of 64 cols

    for (int i = tid; i < HIDDEN; i += 256) b0s[i] = b0[i];

    const size_t arow0 = (size_t)blockIdx.x * MTILE;
    const char* Ag = (const char*)(g_A + arow0 * KDIM);

    // copy addressing: A 64 rows x 16 16B-units; B 128 rows x 16 16B-units
    const int ar = tid >> 2;                 // A row 0..63 (4 units each)
    const int br = tid >> 1;                 // B row 0..127 (8 units each)

    auto copy_chunk = [&](int ch, uint32_t bufo) {
        #pragma unroll
        for (int q = 0; q < 4; q++) {        // A: unit c = (tid&3)*4 + q
            const int c = (tid & 3) * 4 + q;
            const size_t so = (size_t)ar * (KDIM * 4) + ch * 256 + c * 16;
            const uint32_t doff = (c >> 3) * 8192
                                + SMEM_SWIZZLE_128B(ar * 128 + (c & 7) * 16);
            cp_async16(smb + bufo + doff, Ag + so);
        }
        #pragma unroll
        for (int q = 0; q < 8; q++) {        // B: unit c = (tid&1)*8 + q
            const int c = (tid & 1) * 8 + q;
            const size_t so = (size_t)br * (KDIM * 4) + ch * 256 + c * 16;
            const uint32_t doff = 16384 + (c >> 3) * 16384
                                + SMEM_SWIZZLE_128B(br * 128 + (c & 7) * 16);
            cp_async16(smb + bufo + doff, (const char*)g_B + so);
        }
        CP_COMMIT();
    };

    float acc[8][4];
    #pragma unroll
    for (int j = 0; j < 8; j++)
        #pragma unroll
        for (int q = 0; q < 4; q++) acc[j][q] = 0.f;

    // ldmatrix per-thread address patterns
    const int a_row = (lane & 15);              // tiles 0/1: rows, 2/3 repeat
    const int a_off = (lane >> 4) * 16;         // tiles 2/3: +16B (k cols 4-7)
    const int b_row = ((lane >> 4) * 8) + (lane & 7);   // n-rows, +8 for tiles 2/3
    const int b_off = ((lane >> 3) & 1) * 16;   // +16B (k cols 4-7) tiles 1/3

    copy_chunk(0, 0);

    #pragma unroll 1
    for (int ch = 0; ch < NCHUNKS; ch++) {
        const uint32_t bufo = (ch & 1) * BUFSZ;
        if (ch + 1 < NCHUNKS) {
            copy_chunk(ch + 1, ((ch + 1) & 1) * BUFSZ);
            CP_WAIT(1);
        } else {
            CP_WAIT(0);
        }
        __syncthreads();

        #pragma unroll
        for (int ks = 0; ks < 8; ks++) {     // k-step of 8 floats
            const uint32_t plane = (ks >> 2);
            const uint32_t koff  = (ks & 3) * 32;
            uint32_t a0, a1, a2, a3;
            ldsm_x4(smb + bufo + plane * 8192
                        + SMEM_SWIZZLE_128B((mbase + a_row) * 128 + koff + a_off),
                    a0, a1, a2, a3);
            #pragma unroll
            for (int j = 0; j < 4; j++) {    // pairs of n8-tiles
                uint32_t q0, q1, q2, q3;
                ldsm_x4(smb + bufo + 16384 + plane * 16384
                            + SMEM_SWIZZLE_128B((nbase + j * 16 + b_row) * 128
                                                + koff + b_off),
                        q0, q1, q2, q3);
                mma_tf32(acc[2 * j],     a0, a1, a2, a3, q0, q1);
                mma_tf32(acc[2 * j + 1], a0, a1, a2, a3, q2, q3);
            }
        }
        __syncthreads();   // all reads of bufo done before refill (ch+2)
    }

    // ---- epilogue: +bias, ReLU ----
    const int g  = lane >> 2;
    const int tq = lane & 3;
    #pragma unroll
    for (int j = 0; j < 8; j++) {
        const int col = nbase + j * 8 + 2 * tq;
        const float bb0 = b0s[col], bb1 = b0s[col + 1];
        const size_t r0g = arow0 + mbase + g;
        float2 v0 = make_float2(fmaxf(acc[j][0] + bb0, 0.f),
                                fmaxf(acc[j][1] + bb1, 0.f));
        float2 v1 = make_float2(fmaxf(acc[j][2] + bb0, 0.f),
                                fmaxf(acc[j][3] + bb1, 0.f));
        *(float2*)&g_L0[r0g * HIDDEN + col]       = v0;
        *(float2*)&g_L0[(r0g + 8) * HIDDEN + col] = v1;
    }
}

// ============================================================================
// Kernel 3: per root node b:
//   mean_t = ( sum_j 0.5*(neigh_original[b,j,t] - history[neighs1[b,j],t])
//            + sum_i history[h_nodes[b,i],t] ) / 15
//   y = [h1[b] | mean];  out[b] = relu(y @ W1 + b1)
// 128 blocks x 256 threads, W1 staged in smem, 8 roots/block, 4-way split-K.
// ============================================================================
__global__ __launch_bounds__(256)
void final_kernel(const float* __restrict__ history,
                  const float* __restrict__ W1,
                  const float* __restrict__ b1,
                  const int*   __restrict__ neighs1,
                  const int*   __restrict__ h_nodes,
                  float*       __restrict__ out)
{
    extern __shared__ float smf[];
    float* W1s = smf;                        // 16384 floats (64 KB)
    float* ys  = smf + 2 * HIDDEN * NCLASS;  // FB*256
    float* red = ys + FB * 2 * HIDDEN;       // FB*4*64

    const int t   = threadIdx.x;
    const int b0r = blockIdx.x * FB;

    for (int i = t; i < (2 * HIDDEN * NCLASS) / 4; i += 256)
        ((float4*)W1s)[i] = ((const float4*)W1)[i];

    for (int i = t; i < FB * HIDDEN; i += 256) {
        const int r = i >> 7, c = i & 127;
        ys[r * 2 * HIDDEN + c] = g_L0[(size_t)(b0r + r) * HIDDEN + c];
    }

    {
        const int half = t >> 7;
        const int tc   = t & 127;
        #pragma unroll 1
        for (int rr = 0; rr < FB / 2; rr++) {
            const int r = rr * 2 + half;
            const int b = b0r + r;
            float s = 0.f;
            #pragma unroll
            for (int j = 0; j < K1; j++) {
                const int n1 = neighs1[b * K1 + j];
                const float no = g_L0[(size_t)(BATCH + b * K1 + j) * HIDDEN + tc];
                s += 0.5f * (no - history[(size_t)n1 * HIDDEN + tc]);
            }
            #pragma unroll
            for (int j = 0; j < NHIST; j++) {
                const int hn = h_nodes[b * NHIST + j];
                s += history[(size_t)hn * HIDDEN + tc];
            }
            ys[r * 2 * HIDDEN + HIDDEN + tc] = s * (1.f / (K1 + NHIST));
        }
    }
    __syncthreads();

    const int o  = t & 63;
    const int s4 = t >> 6;
    float acc[FB];
    #pragma unroll
    for (int r = 0; r < FB; r++) acc[r] = 0.f;
    #pragma unroll 4
    for (int kk = 0; kk < (2 * HIDDEN) / 4; kk++) {
        const int k = s4 * ((2 * HIDDEN) / 4) + kk;
        const float wv = W1s[k * NCLASS + o];
        #pragma unroll
        for (int r = 0; r < FB; r++)
            acc[r] += ys[r * 2 * HIDDEN + k] * wv;
    }
    #pragma unroll
    for (int r = 0; r < FB; r++) red[(r * 4 + s4) * 64 + o] = acc[r];
    __syncthreads();

    for (int i = t; i < FB * NCLASS; i += 256) {
        const int r = i >> 6, o2 = i & 63;
        const float v = red[(r * 4 + 0) * 64 + o2] + red[(r * 4 + 1) * 64 + o2]
                      + red[(r * 4 + 2) * 64 + o2] + red[(r * 4 + 3) * 64 + o2];
        out[(size_t)(b0r + r) * NCLASS + o2] = fmaxf(v + b1[o2], 0.f);
    }
}

// ============================================================================
// kernel_launch — graph-capturable, allocation-free.
// Input order: feats, history, W0, b0, W1, b1, nodes, neighs0, neighs1,
// neighs0_nb, h_nodes. Output: float32 [1024, 64].
// ============================================================================
extern "C" void kernel_launch(void* const* d_in, const int* in_sizes, int n_in,
                              void* d_out, int out_size)
{
    const float* feats      = (const float*)d_in[0];
    const float* history    = (const float*)d_in[1];
    const float* W0         = (const float*)d_in[2];
    const float* b0         = (const float*)d_in[3];
    const float* W1         = (const float*)d_in[4];
    const float* b1         = (const float*)d_in[5];
    const int*   nodes      = (const int*)d_in[6];
    const int*   neighs0    = (const int*)d_in[7];
    const int*   neighs1    = (const int*)d_in[8];
    const int*   neighs0_nb = (const int*)d_in[9];
    const int*   h_nodes    = (const int*)d_in[10];
    float* out = (float*)d_out;

    const int gemm_smem  = 2 * BUFSZ + 512;   // 96.5 KB
    const int final_smem = (2 * HIDDEN * NCLASS + FB * 2 * HIDDEN + FB * 4 * 64)
                           * (int)sizeof(float);   // 80 KB
    cudaFuncSetAttribute(gemm_kernel, cudaFuncAttributeMaxDynamicSharedMemorySize,
                         gemm_smem);
    cudaFuncSetAttribute(final_kernel, cudaFuncAttributeMaxDynamicSharedMemorySize,
                         final_smem);

    gather_kernel<<<GROWBLK + WBLK, 128>>>(feats, W0, nodes, neighs0, neighs1,
                                           neighs0_nb);
    gemm_kernel<<<GEMM_NBLK, 256, gemm_smem>>>(b0);
    final_kernel<<<FNBLK, 256, final_smem>>>(history, W1, b1, neighs1, h_nodes, out);
}

// round 12
// speedup vs baseline: 1.9564x; 1.2940x over previous
#include <cuda_runtime.h>
#include <cuda_bf16.h>
#include <cstdint>

// Problem constants (fixed shapes from the reference)
#define N_NODES   100000
#define NFEATS    256
#define HIDDEN    128
#define NCLASS    64
#define BATCH     1024
#define K0        25
#define K1        10
#define NHIST     5
#define ROWS_TOTAL (BATCH + BATCH * K1)   // 11264 layer0 rows
#define GROWBLK    (ROWS_TOTAL / 2)        // 5632 gather blocks (2 rows each)
#define WBLK       8                       // extra blocks for W0 transpose
#define MTILE      64                      // GEMM M tile
#define MT_TOTAL   (ROWS_TOTAL / MTILE)    // 176 m-tiles
#define HALF_BLOCKS 74                     // blocks per N-half (148 total)
#define KDIM       (2 * NFEATS)            // 512
#define KCHUNK     64                      // 64 f32 = 256 B/row = 2 x 128B planes
#define NCHUNKS    (KDIM / KCHUNK)         // 8
#define FB         4                       // roots per block in final kernel
#define FNBLK      (BATCH / FB)            // 256 blocks
// GEMM smem map: B-half 128K | 5 A-stages x 16K | bias
#define SA_OFF     131072
#define B0_OFF     (SA_OFF + 5 * 16384)    // 212992
#define GEMM_SMEM  (B0_OFF + 512)          // 213504

// ---------------- device scratch ----------------
__device__ __align__(16) float g_L0[(size_t)ROWS_TOTAL * HIDDEN];
__device__ __align__(16) float g_A[(size_t)ROWS_TOTAL * KDIM];   // tf32-rounded x
__device__ __align__(16) float g_B[(size_t)HIDDEN * KDIM];       // tf32 W0^T [n][k]

#define SMEM_SWIZZLE_128B(o) ((o) ^ (((o) >> 3) & 0x70))

__device__ __forceinline__ uint32_t smem_to_u32(const void* p) {
    uint32_t a;
    asm("{ .reg .u64 t; cvta.to.shared.u64 t, %1; cvt.u32.u64 %0, t; }" : "=r"(a) : "l"(p));
    return a;
}
__device__ __forceinline__ float tf32_rna(float x) {
    uint32_t r;
    asm("cvt.rna.tf32.f32 %0, %1;" : "=r"(r) : "f"(x));
    return __uint_as_float(r);
}
__device__ __forceinline__ void cp_async16(uint32_t dst, const void* src) {
    asm volatile("cp.async.cg.shared.global [%0], [%1], 16;" :: "r"(dst), "l"(src));
}
#define CP_COMMIT()  asm volatile("cp.async.commit_group;" ::: "memory")
#define CP_WAIT(n)   asm volatile("cp.async.wait_group %0;" :: "n"(n) : "memory")

__device__ __forceinline__ void ldsm_x4(uint32_t addr, uint32_t& r0, uint32_t& r1,
                                        uint32_t& r2, uint32_t& r3) {
    asm volatile("ldmatrix.sync.aligned.m8n8.x4.shared.b16 {%0,%1,%2,%3}, [%4];"
                 : "=r"(r0), "=r"(r1), "=r"(r2), "=r"(r3) : "r"(addr));
}
__device__ __forceinline__ void mma_tf32(float* d, uint32_t a0, uint32_t a1,
                                         uint32_t a2, uint32_t a3,
                                         uint32_t b0, uint32_t b1) {
    asm volatile(
        "mma.sync.aligned.m16n8k8.row.col.f32.tf32.tf32.f32 "
        "{%0,%1,%2,%3}, {%4,%5,%6,%7}, {%8,%9}, {%0,%1,%2,%3};"
        : "+f"(d[0]), "+f"(d[1]), "+f"(d[2]), "+f"(d[3])
        : "r"(a0), "r"(a1), "r"(a2), "r"(a3), "r"(b0), "r"(b1));
}

// ============================================================================
// Kernel 1: gather + mean -> tf32-rounded fp32 scratch. (unchanged from R10:
// 35.4 us, near compulsory-traffic floor)
// ============================================================================
__global__ __launch_bounds__(128)
void gather_kernel(const float* __restrict__ feats,
                   const float* __restrict__ W0,
                   const int*   __restrict__ nodes,
                   const int*   __restrict__ neighs0,
                   const int*   __restrict__ neighs1,
                   const int*   __restrict__ neighs0_nb)
{
    const int t = threadIdx.x;

    if (blockIdx.x >= GROWBLK) {        // ---- W0 transpose (tf32), full 64K ----
        const int b = blockIdx.x - GROWBLK;
        #pragma unroll 4
        for (int j = 0; j < 64; j++) {
            const int idx = b * 8192 + j * 128 + t;   // idx = k*128 + n
            const int k = idx >> 7, n = idx & 127;
            g_B[(size_t)n * KDIM + k] = tf32_rna(W0[idx]);
        }
        return;
    }

    const int half = t >> 6;
    const int tc   = t & 63;
    const int row  = blockIdx.x * 2 + half;
    const float4* f4 = (const float4*)feats;

    int self;
    const int* nb;
    if (row < BATCH) {
        self = nodes[row];
        nb   = neighs0 + row * K0;
    } else {
        const int j = row - BATCH;
        self = neighs1[j];
        nb   = neighs0_nb + j * K0;
    }
    const float4 sv = f4[(size_t)self * (NFEATS / 4) + tc];
    float s0 = 0.f, s1 = 0.f, s2 = 0.f, s3 = 0.f;
    #pragma unroll
    for (int k = 0; k < K0; k++) {
        const float4 v = f4[(size_t)nb[k] * (NFEATS / 4) + tc];
        s0 += v.x; s1 += v.y; s2 += v.z; s3 += v.w;
    }
    const float inv = 1.f / K0;

    float4* A4 = (float4*)(g_A + (size_t)row * KDIM);
    A4[tc] = make_float4(tf32_rna(sv.x), tf32_rna(sv.y),
                         tf32_rna(sv.z), tf32_rna(sv.w));
    A4[64 + tc] = make_float4(tf32_rna(s0 * inv), tf32_rna(s1 * inv),
                              tf32_rna(s2 * inv), tf32_rna(s3 * inv));
}

// ============================================================================
// Kernel 2: PERSISTENT-B TF32 GEMM. grid 148 x 512 threads (16 warps/SM on
// every SM; no straggler wave).
// Block bid: nh = bid&1 (N-half of 64 cols), slot = bid>>1 (0..73).
// - Stage B-half [64 n][512 k] (128 KB) in smem ONCE  (B L2 traffic 45->19 MB)
// - Loop m-tiles mt = slot, slot+74, ... (<176): stream A chunks through a
//   5-stage 16 KB cp.async pipeline; one __syncthreads per chunk.
// Group-count invariant: after committing in iter ch, exactly 4 groups are
// younger than A_ch  ->  CP_WAIT(4) guarantees A_ch (and B) complete.
// Warp (w&3, w>>2): 16 rows x 16 cols; per ks one A-ldsm + one B-ldsm + 2 mma.
// ============================================================================
__global__ __launch_bounds__(512)
void gemm_kernel(const float* __restrict__ b0)
{
    extern __shared__ __align__(1024) char sm[];
    float* b0s = (float*)(sm + B0_OFF);
    const uint32_t smb = smem_to_u32(sm);
    const int tid  = threadIdx.x;
    const int lane = tid & 31;
    const int w    = tid >> 5;
    const int wm   = (w & 3) * 16;      // m-strip
    const int wn   = (w >> 2) * 16;     // n-strip within half
    const int nh   = blockIdx.x & 1;
    const int slot = blockIdx.x >> 1;   // 0..73

    for (int i = tid; i < HIDDEN; i += 512) b0s[i] = b0[i];

    // ---- stage B-half once: 8192 x 16B units, 16 per thread ----
    {
        const char* Bh = (const char*)(g_B + (size_t)(nh * 64) * KDIM);
        #pragma unroll
        for (int q = 0; q < 16; q++) {
            const int id = tid + 512 * q;        // 0..8191
            const int r = id >> 7, c = id & 127; // n-row, 16B-unit
            const uint32_t doff = (c >> 3) * 8192
                                + SMEM_SWIZZLE_128B(r * 128 + (c & 7) * 16);
            cp_async16(smb + doff, Bh + (size_t)r * 2048 + c * 16);
        }
        CP_COMMIT();                             // group: B
    }

    // ldmatrix per-thread patterns (validated in R10)
    const int a_row = (lane & 15);
    const int a_off = (lane >> 4) * 16;
    const int b_row = ((lane >> 4) * 8) + (lane & 7);
    const int b_off = ((lane >> 3) & 1) * 16;

    for (int mt = slot; mt < MT_TOTAL; mt += HALF_BLOCKS) {
        const size_t arow0 = (size_t)mt * MTILE;
        const char* Ag = (const char*)(g_A + arow0 * KDIM);

        // A chunk copy: 1024 x 16B units, 2 per thread, into stage s
        auto copyA = [&](int ch, int s) {
            #pragma unroll
            for (int q = 0; q < 2; q++) {
                const int id = tid + 512 * q;    // 0..1023
                const int r = id >> 4, c = id & 15;
                const uint32_t doff = SA_OFF + s * 16384 + (c >> 3) * 8192
                                    + SMEM_SWIZZLE_128B(r * 128 + (c & 7) * 16);
                cp_async16(smb + doff, Ag + (size_t)r * 2048 + ch * 256 + c * 16);
            }
        };

        // prologue: stages 0..3 <- chunks 0..3 (4 groups)
        copyA(0, 0); CP_COMMIT();
        copyA(1, 1); CP_COMMIT();
        copyA(2, 2); CP_COMMIT();
        copyA(3, 3); CP_COMMIT();

        float acc[2][4];
        #pragma unroll
        for (int j = 0; j < 2; j++)
            #pragma unroll
            for (int q = 0; q < 4; q++) acc[j][q] = 0.f;

        #pragma unroll 1
        for (int ch = 0; ch < NCHUNKS; ch++) {
            if (ch + 4 < NCHUNKS) copyA(ch + 4, (ch + 4) % 5);
            CP_COMMIT();                 // always commit (possibly empty group)
            CP_WAIT(4);                  // => A_ch (and B) complete
            __syncthreads();

            const uint32_t sa = smb + SA_OFF + (ch % 5) * 16384;
            #pragma unroll
            for (int ks = 0; ks < 8; ks++) {
                const uint32_t koff = (ks & 3) * 32;
                uint32_t a0, a1, a2, a3;
                ldsm_x4(sa + (ks >> 2) * 8192
                            + SMEM_SWIZZLE_128B((wm + a_row) * 128 + koff + a_off),
                        a0, a1, a2, a3);
                uint32_t q0, q1, q2, q3;
                ldsm_x4(smb + (ch * 2 + (ks >> 2)) * 8192
                            + SMEM_SWIZZLE_128B((wn + b_row) * 128 + koff + b_off),
                        q0, q1, q2, q3);
                mma_tf32(acc[0], a0, a1, a2, a3, q0, q1);
                mma_tf32(acc[1], a0, a1, a2, a3, q2, q3);
            }
        }

        // ---- epilogue: +bias, ReLU -> g_L0 ----
        {
            const int g  = lane >> 2;
            const int tq = lane & 3;
            #pragma unroll
            for (int j = 0; j < 2; j++) {
                const int col = nh * 64 + wn + j * 8 + 2 * tq;
                const float bb0 = b0s[col], bb1 = b0s[col + 1];
                const size_t r0g = arow0 + wm + g;
                float2 v0 = make_float2(fmaxf(acc[j][0] + bb0, 0.f),
                                        fmaxf(acc[j][1] + bb1, 0.f));
                float2 v1 = make_float2(fmaxf(acc[j][2] + bb0, 0.f),
                                        fmaxf(acc[j][3] + bb1, 0.f));
                *(float2*)&g_L0[r0g * HIDDEN + col]       = v0;
                *(float2*)&g_L0[(r0g + 8) * HIDDEN + col] = v1;
            }
        }
        __syncthreads();   // all reads done before next tile's prologue refill
    }
}

// ============================================================================
// Kernel 3: final layer. FB=4 roots/block, grid 256 (~2 blocks/SM), 256 thr,
// W1 staged in smem, 4-way split-K.
// ============================================================================
__global__ __launch_bounds__(256)
void final_kernel(const float* __restrict__ history,
                  const float* __restrict__ W1,
                  const float* __restrict__ b1,
                  const int*   __restrict__ neighs1,
                  const int*   __restrict__ h_nodes,
                  float*       __restrict__ out)
{
    extern __shared__ float smf[];
    float* W1s = smf;                        // 16384 floats (64 KB)
    float* ys  = smf + 2 * HIDDEN * NCLASS;  // FB*256
    float* red = ys + FB * 2 * HIDDEN;       // FB*4*64

    const int t   = threadIdx.x;
    const int b0r = blockIdx.x * FB;

    for (int i = t; i < (2 * HIDDEN * NCLASS) / 4; i += 256)
        ((float4*)W1s)[i] = ((const float4*)W1)[i];

    for (int i = t; i < FB * HIDDEN; i += 256) {
        const int r = i >> 7, c = i & 127;
        ys[r * 2 * HIDDEN + c] = g_L0[(size_t)(b0r + r) * HIDDEN + c];
    }

    {
        const int half = t >> 7;
        const int tc   = t & 127;
        #pragma unroll 1
        for (int rr = 0; rr < FB / 2; rr++) {
            const int r = rr * 2 + half;
            const int b = b0r + r;
            float s = 0.f;
            #pragma unroll
            for (int j = 0; j < K1; j++) {
                const int n1 = neighs1[b * K1 + j];
                const float no = g_L0[(size_t)(BATCH + b * K1 + j) * HIDDEN + tc];
                s += 0.5f * (no - history[(size_t)n1 * HIDDEN + tc]);
            }
            #pragma unroll
            for (int j = 0; j < NHIST; j++) {
                const int hn = h_nodes[b * NHIST + j];
                s += history[(size_t)hn * HIDDEN + tc];
            }
            ys[r * 2 * HIDDEN + HIDDEN + tc] = s * (1.f / (K1 + NHIST));
        }
    }
    __syncthreads();

    const int o  = t & 63;
    const int s4 = t >> 6;
    float acc[FB];
    #pragma unroll
    for (int r = 0; r < FB; r++) acc[r] = 0.f;
    #pragma unroll 4
    for (int kk = 0; kk < (2 * HIDDEN) / 4; kk++) {
        const int k = s4 * ((2 * HIDDEN) / 4) + kk;
        const float wv = W1s[k * NCLASS + o];
        #pragma unroll
        for (int r = 0; r < FB; r++)
            acc[r] += ys[r * 2 * HIDDEN + k] * wv;
    }
    #pragma unroll
    for (int r = 0; r < FB; r++) red[(r * 4 + s4) * 64 + o] = acc[r];
    __syncthreads();

    for (int i = t; i < FB * NCLASS; i += 256) {
        const int r = i >> 6, o2 = i & 63;
        const float v = red[(r * 4 + 0) * 64 + o2] + red[(r * 4 + 1) * 64 + o2]
                      + red[(r * 4 + 2) * 64 + o2] + red[(r * 4 + 3) * 64 + o2];
        out[(size_t)(b0r + r) * NCLASS + o2] = fmaxf(v + b1[o2], 0.f);
    }
}

// ============================================================================
// kernel_launch — graph-capturable, allocation-free.
// Input order: feats, history, W0, b0, W1, b1, nodes, neighs0, neighs1,
// neighs0_nb, h_nodes. Output: float32 [1024, 64].
// ============================================================================
extern "C" void kernel_launch(void* const* d_in, const int* in_sizes, int n_in,
                              void* d_out, int out_size)
{
    const float* feats      = (const float*)d_in[0];
    const float* history    = (const float*)d_in[1];
    const float* W0         = (const float*)d_in[2];
    const float* b0         = (const float*)d_in[3];
    const float* W1         = (const float*)d_in[4];
    const float* b1         = (const float*)d_in[5];
    const int*   nodes      = (const int*)d_in[6];
    const int*   neighs0    = (const int*)d_in[7];
    const int*   neighs1    = (const int*)d_in[8];
    const int*   neighs0_nb = (const int*)d_in[9];
    const int*   h_nodes    = (const int*)d_in[10];
    float* out = (float*)d_out;

    const int final_smem = (2 * HIDDEN * NCLASS + FB * 2 * HIDDEN + FB * 4 * 64)
                           * (int)sizeof(float);   // 72 KB
    cudaFuncSetAttribute(gemm_kernel, cudaFuncAttributeMaxDynamicSharedMemorySize,
                         GEMM_SMEM);
    cudaFuncSetAttribute(final_kernel, cudaFuncAttributeMaxDynamicSharedMemorySize,
                         final_smem);

    gather_kernel<<<GROWBLK + WBLK, 128>>>(feats, W0, nodes, neighs0, neighs1,
                                           neighs0_nb);
    gemm_kernel<<<2 * HALF_BLOCKS, 512, GEMM_SMEM>>>(b0);
    final_kernel<<<FNBLK, 256, final_smem>>>(history, W1, b1, neighs1, h_nodes, out);
}